// round 2
// baseline (speedup 1.0000x reference)
#include <cuda_runtime.h>
#include <cstdint>
#include <cstddef>

#define TT   2048
#define BB   64
#define SS   256
#define INK  64
#define DK   32
#define WK   (INK + DK)      // 96
#define CCH  64              // chunks
#define LCH  32              // chunk length (TT/CCH)
#define BT   16              // batch tile for pass1/pass3
#define NBT  (BB / BT)       // 4
#define TBS  (TT * BB * SS)  // 33,554,432

// ---------------- device scratch (static; no runtime allocation) ----------------
__device__ float g_At[SS * SS];            // At[k][s] = A[s][k]
__device__ float g_Wt[WK * SS];            // Wt[i][s] = packed [Bw^T ; Ew^T]
__device__ float g_PA[SS * SS];            // power ping
__device__ float g_PB[SS * SS];            // power pong
__device__ float g_drive[TBS];             // drive[t,b,s]
__device__ float g_localEnd[(CCH - 1) * BB * SS];
__device__ float g_xstart[CCH * BB * SS];

// ---------------- packed f32x2 helpers ----------------
__device__ __forceinline__ void fma2(unsigned long long& acc,
                                     unsigned long long a, unsigned long long b) {
    asm("fma.rn.f32x2 %0, %1, %2, %0;" : "+l"(acc) : "l"(a), "l"(b));
}
__device__ __forceinline__ void add2(unsigned long long& acc, unsigned long long a) {
    asm("add.rn.f32x2 %0, %1, %0;" : "+l"(acc) : "l"(a));
}
__device__ __forceinline__ unsigned long long pack2(float lo, float hi) {
    unsigned long long r;
    asm("mov.b64 %0, {%1, %2};" : "=l"(r) : "f"(lo), "f"(hi));
    return r;
}
__device__ __forceinline__ float2 unpack2(unsigned long long v) {
    float2 f;
    asm("mov.b64 {%0, %1}, %2;" : "=f"(f.x), "=f"(f.y) : "l"(v));
    return f;
}

// ---------------- prep: transpose A, pack weights ----------------
__global__ void __launch_bounds__(256) k_prep(const float* __restrict__ A,
                                              const float* __restrict__ Bw,
                                              const float* __restrict__ Ew) {
    int idx = blockIdx.x * blockDim.x + threadIdx.x;
    if (idx < SS * SS) {
        int k = idx / SS, s = idx % SS;
        g_At[idx] = A[s * SS + k];
    } else {
        int j = idx - SS * SS;
        if (j < WK * SS) {
            int i = j / SS, s = j % SS;
            g_Wt[j] = (i < INK) ? Bw[s * INK + i] : Ew[s * DK + (i - INK)];
        }
    }
}

// ---------------- drive: g_drive[t,b,s] = U@Bw^T + D@Ew^T ----------------
__global__ void __launch_bounds__(256) k_drive(const float* __restrict__ U,
                                               const float* __restrict__ D) {
    __shared__ __align__(16) float sRow[WK][36];  // [i][r], 144B row stride
    const int R0 = blockIdx.x * 32;               // 32 flattened (t,b) rows per CTA
    const int s  = threadIdx.x;

    for (int e = threadIdx.x; e < 32 * WK; e += 256) {
        int r = e / WK, i = e % WK;
        size_t R = (size_t)(R0 + r);
        sRow[i][r] = (i < INK) ? U[R * INK + i] : D[R * DK + (i - INK)];
    }
    __syncthreads();

    unsigned long long acc[16];
#pragma unroll
    for (int p = 0; p < 16; ++p) acc[p] = 0ull;

    const float* wp = g_Wt + s;
#pragma unroll 4
    for (int i = 0; i < WK; ++i) {
        float w = wp[(size_t)i * SS];
        unsigned long long w2 = pack2(w, w);
        const ulonglong2* xv = (const ulonglong2*)(&sRow[i][0]);
#pragma unroll
        for (int q = 0; q < 8; ++q) {
            ulonglong2 v = xv[q];
            fma2(acc[2 * q],     v.x, w2);
            fma2(acc[2 * q + 1], v.y, w2);
        }
    }
#pragma unroll
    for (int p = 0; p < 16; ++p) {
        float2 f = unpack2(acc[p]);
        size_t base = (size_t)(R0 + 2 * p) * SS + s;
        g_drive[base]      = f.x;
        g_drive[base + SS] = f.y;
    }
}

// ---------------- square: dst = src @ src (row-major 256x256) ----------------
// mode 0: At->PA, 1: PA->PB, 2: PB->PA, 3: PA->PB, 4: PB->PA  (result = At^32 in PA)
__global__ void __launch_bounds__(256) k_square(int mode) {
    const float* src = (mode == 0) ? g_At : ((mode & 1) ? g_PA : g_PB);
    float*       dst = (mode & 1) ? g_PB : g_PA;

    __shared__ float sRow[2][SS];
    const int tid = threadIdx.x;
    const int k0  = blockIdx.x * 2;

    sRow[0][tid] = src[(size_t)k0 * SS + tid];
    sRow[1][tid] = src[(size_t)(k0 + 1) * SS + tid];
    __syncthreads();

    float a0 = 0.f, a1 = 0.f;
#pragma unroll 4
    for (int j = 0; j < SS; ++j) {
        float b = src[(size_t)j * SS + tid];
        a0 = fmaf(sRow[0][j], b, a0);
        a1 = fmaf(sRow[1][j], b, a1);
    }
    dst[(size_t)k0 * SS + tid]       = a0;
    dst[(size_t)(k0 + 1) * SS + tid] = a1;
}

// ---------------- pass1: per-chunk zero-init scan, keep only chunk-end ----------------
__global__ void __launch_bounds__(256) k_pass1() {
    const int c  = blockIdx.x / NBT;            // chunk 0..CCH-2
    const int b0 = (blockIdx.x % NBT) * BT;
    const int s  = threadIdx.x;
    __shared__ __align__(16) float sx[SS][20];  // [k][r], 80B row stride (16B-aligned)

#pragma unroll
    for (int r = 0; r < BT; ++r) sx[s][r] = 0.f;
    __syncthreads();

    for (int j = 0; j < LCH; ++j) {
        const int t = c * LCH + j;
        unsigned long long acc[8];
#pragma unroll
        for (int p = 0; p < 8; ++p) acc[p] = 0ull;

        const float* wp = g_At + s;
#pragma unroll 4
        for (int k = 0; k < SS; ++k) {
            float w = wp[(size_t)k * SS];
            unsigned long long w2 = pack2(w, w);
            const ulonglong2* xv = (const ulonglong2*)(&sx[k][0]);
            ulonglong2 v0 = xv[0], v1 = xv[1], v2 = xv[2], v3 = xv[3];
            fma2(acc[0], v0.x, w2); fma2(acc[1], v0.y, w2);
            fma2(acc[2], v1.x, w2); fma2(acc[3], v1.y, w2);
            fma2(acc[4], v2.x, w2); fma2(acc[5], v2.y, w2);
            fma2(acc[6], v3.x, w2); fma2(acc[7], v3.y, w2);
        }
        const float* dr = g_drive + ((size_t)t * BB + b0) * SS + s;
#pragma unroll
        for (int p = 0; p < 8; ++p) {
            unsigned long long d2 = pack2(dr[(size_t)(2 * p) * SS],
                                          dr[(size_t)(2 * p + 1) * SS]);
            add2(acc[p], d2);
        }
        __syncthreads();
        ulonglong2* qd = (ulonglong2*)(&sx[s][0]);
        qd[0] = make_ulonglong2(acc[0], acc[1]);
        qd[1] = make_ulonglong2(acc[2], acc[3]);
        qd[2] = make_ulonglong2(acc[4], acc[5]);
        qd[3] = make_ulonglong2(acc[6], acc[7]);
        __syncthreads();
    }
#pragma unroll
    for (int r = 0; r < BT; ++r)
        g_localEnd[((size_t)c * BB + b0 + r) * SS + s] = sx[s][r];
}

// ---------------- pass2: boundary recurrence (independent per batch row) ----------------
__global__ void __launch_bounds__(256) k_pass2(const float* __restrict__ x0) {
    const int b0 = blockIdx.x * 2;   // 32 CTAs x 2 batch rows
    const int s  = threadIdx.x;
    __shared__ __align__(8) float sxp[SS][2];

    float v0 = x0[(size_t)b0 * SS + s];
    float v1 = x0[(size_t)(b0 + 1) * SS + s];
    sxp[s][0] = v0; sxp[s][1] = v1;
    g_xstart[((size_t)0 * BB + b0) * SS + s]     = v0;
    g_xstart[((size_t)0 * BB + b0 + 1) * SS + s] = v1;
    __syncthreads();

    for (int c = 1; c < CCH; ++c) {
        unsigned long long acc[4];
#pragma unroll
        for (int u = 0; u < 4; ++u) acc[u] = 0ull;
        const float* wp = g_PA + s;   // (A^T)^32, row-major [k][s]
#pragma unroll 2
        for (int k = 0; k < SS; k += 4) {
#pragma unroll
            for (int u = 0; u < 4; ++u) {
                float w = wp[(size_t)(k + u) * SS];
                unsigned long long w2 = pack2(w, w);
                unsigned long long xp = *(const unsigned long long*)(&sxp[k + u][0]);
                fma2(acc[u], xp, w2);
            }
        }
        add2(acc[0], acc[1]); add2(acc[2], acc[3]); add2(acc[0], acc[2]);
        float2 f = unpack2(acc[0]);
        f.x += g_localEnd[((size_t)(c - 1) * BB + b0) * SS + s];
        f.y += g_localEnd[((size_t)(c - 1) * BB + b0 + 1) * SS + s];
        __syncthreads();
        sxp[s][0] = f.x; sxp[s][1] = f.y;
        __syncthreads();
        g_xstart[((size_t)c * BB + b0) * SS + s]     = f.x;
        g_xstart[((size_t)c * BB + b0 + 1) * SS + s] = f.y;
    }
}

// ---------------- pass3: real scan per chunk from exact starts, emit X ----------------
__global__ void __launch_bounds__(256) k_pass3(float* __restrict__ out, int dup) {
    const int c  = blockIdx.x / NBT;            // chunk 0..CCH-1
    const int b0 = (blockIdx.x % NBT) * BT;
    const int s  = threadIdx.x;
    __shared__ __align__(16) float sx[SS][20];

#pragma unroll
    for (int r = 0; r < BT; ++r)
        sx[s][r] = g_xstart[((size_t)c * BB + b0 + r) * SS + s];
    __syncthreads();

    float* out2 = out + (size_t)TBS;

    for (int j = 0; j < LCH; ++j) {
        const int t = c * LCH + j;
        unsigned long long acc[8];
#pragma unroll
        for (int p = 0; p < 8; ++p) acc[p] = 0ull;

        const float* wp = g_At + s;
#pragma unroll 4
        for (int k = 0; k < SS; ++k) {
            float w = wp[(size_t)k * SS];
            unsigned long long w2 = pack2(w, w);
            const ulonglong2* xv = (const ulonglong2*)(&sx[k][0]);
            ulonglong2 v0 = xv[0], v1 = xv[1], v2 = xv[2], v3 = xv[3];
            fma2(acc[0], v0.x, w2); fma2(acc[1], v0.y, w2);
            fma2(acc[2], v1.x, w2); fma2(acc[3], v1.y, w2);
            fma2(acc[4], v2.x, w2); fma2(acc[5], v2.y, w2);
            fma2(acc[6], v3.x, w2); fma2(acc[7], v3.y, w2);
        }
        const float* dr = g_drive + ((size_t)t * BB + b0) * SS + s;
#pragma unroll
        for (int p = 0; p < 8; ++p) {
            unsigned long long d2 = pack2(dr[(size_t)(2 * p) * SS],
                                          dr[(size_t)(2 * p + 1) * SS]);
            add2(acc[p], d2);
        }
        __syncthreads();
        ulonglong2* qd = (ulonglong2*)(&sx[s][0]);
        qd[0] = make_ulonglong2(acc[0], acc[1]);
        qd[1] = make_ulonglong2(acc[2], acc[3]);
        qd[2] = make_ulonglong2(acc[4], acc[5]);
        qd[3] = make_ulonglong2(acc[6], acc[7]);
        __syncthreads();

        size_t obase = ((size_t)t * BB + b0) * SS + s;
#pragma unroll
        for (int p = 0; p < 8; ++p) {
            float2 f = unpack2(acc[p]);
            size_t o0 = obase + (size_t)(2 * p) * SS;
            size_t o1 = obase + (size_t)(2 * p + 1) * SS;
            out[o0] = f.x; out[o1] = f.y;
            if (dup) { out2[o0] = f.x; out2[o1] = f.y; }
        }
    }
}

// ---------------- launcher ----------------
extern "C" void kernel_launch(void* const* d_in, const int* in_sizes, int n_in,
                              void* d_out, int out_size) {
    const float* x  = (const float*)d_in[0];
    const float* U  = (const float*)d_in[1];
    const float* D  = (const float*)d_in[2];
    const float* Aw = (const float*)d_in[3];
    const float* Bw = (const float*)d_in[4];
    const float* Ew = (const float*)d_in[5];
    float* out = (float*)d_out;
    int dup = (out_size >= 2 * TBS) ? 1 : 0;

    k_prep<<<(SS * SS + WK * SS + 255) / 256, 256>>>(Aw, Bw, Ew);
    k_drive<<<(TT * BB) / 32, 256>>>(U, D);
    for (int m = 0; m < 5; ++m) k_square<<<SS / 2, 256>>>(m);
    k_pass1<<<(CCH - 1) * NBT, 256>>>();
    k_pass2<<<BB / 2, 256>>>(x);
    k_pass3<<<CCH * NBT, 256>>>(out, dup);
}

// round 3
// speedup vs baseline: 1.1347x; 1.1347x over previous
#include <cuda_runtime.h>
#include <cstdint>
#include <cstddef>

#define TT   2048
#define BB   64
#define SS   256
#define INK  64
#define DK   32
#define WK   (INK + DK)      // 96
#define CCH  64              // chunks
#define LCH  32              // chunk length (TT/CCH)
#define BT   32              // batch tile for pass1/pass3
#define NBT  (BB / BT)       // 2
#define TBS  (TT * BB * SS)  // 33,554,432
#define PAD  36              // smem row stride (floats) for sx

// ---------------- device scratch (static; no runtime allocation) ----------------
__device__ float g_At[SS * SS];            // At[k][s] = A[s][k]
__device__ float g_Wt[WK * SS];            // Wt[i][s] = packed [Bw^T ; Ew^T]
__device__ float g_PA[SS * SS];            // power ping
__device__ float g_PB[SS * SS];            // power pong
__device__ float g_drive[TBS];             // drive[t,b,s]
__device__ float g_localEnd[(CCH - 1) * BB * SS];
__device__ float g_xstart[CCH * BB * SS];
__device__ unsigned g_sync;

// ---------------- packed f32x2 helpers ----------------
__device__ __forceinline__ void fma2(unsigned long long& acc,
                                     unsigned long long a, unsigned long long b) {
    asm("fma.rn.f32x2 %0, %1, %2, %0;" : "+l"(acc) : "l"(a), "l"(b));
}
__device__ __forceinline__ void add2(unsigned long long& acc, unsigned long long a) {
    asm("add.rn.f32x2 %0, %1, %0;" : "+l"(acc) : "l"(a));
}
__device__ __forceinline__ unsigned long long pack2(float lo, float hi) {
    unsigned long long r;
    asm("mov.b64 %0, {%1, %2};" : "=l"(r) : "f"(lo), "f"(hi));
    return r;
}
__device__ __forceinline__ float2 unpack2(unsigned long long v) {
    float2 f;
    asm("mov.b64 {%0, %1}, %2;" : "=f"(f.x), "=f"(f.y) : "l"(v));
    return f;
}

// ---------------- prep: transpose A, pack weights, reset barrier ----------------
__global__ void __launch_bounds__(256) k_prep(const float* __restrict__ A,
                                              const float* __restrict__ Bw,
                                              const float* __restrict__ Ew) {
    int idx = blockIdx.x * blockDim.x + threadIdx.x;
    if (idx == 0) g_sync = 0u;
    if (idx < SS * SS) {
        int k = idx / SS, s = idx % SS;
        g_At[idx] = A[s * SS + k];
    } else {
        int j = idx - SS * SS;
        if (j < WK * SS) {
            int i = j / SS, s = j % SS;
            g_Wt[j] = (i < INK) ? Bw[s * INK + i] : Ew[s * DK + (i - INK)];
        }
    }
}

// ---------------- drive: g_drive[t,b,s] = U@Bw^T + D@Ew^T ----------------
__global__ void __launch_bounds__(256) k_drive(const float* __restrict__ U,
                                               const float* __restrict__ D) {
    __shared__ __align__(16) float sRow[WK][36];
    const int R0 = blockIdx.x * 32;
    const int s  = threadIdx.x;

    for (int e = threadIdx.x; e < 32 * WK; e += 256) {
        int r = e / WK, i = e % WK;
        size_t R = (size_t)(R0 + r);
        sRow[i][r] = (i < INK) ? U[R * INK + i] : D[R * DK + (i - INK)];
    }
    __syncthreads();

    unsigned long long acc[16];
#pragma unroll
    for (int p = 0; p < 16; ++p) acc[p] = 0ull;

    const float* wp = g_Wt + s;
#pragma unroll 4
    for (int i = 0; i < WK; ++i) {
        float w = wp[(size_t)i * SS];
        unsigned long long w2 = pack2(w, w);
        const ulonglong2* xv = (const ulonglong2*)(&sRow[i][0]);
#pragma unroll
        for (int q = 0; q < 8; ++q) {
            ulonglong2 v = xv[q];
            fma2(acc[2 * q],     v.x, w2);
            fma2(acc[2 * q + 1], v.y, w2);
        }
    }
#pragma unroll
    for (int p = 0; p < 16; ++p) {
        float2 f = unpack2(acc[p]);
        size_t base = (size_t)(R0 + 2 * p) * SS + s;
        g_drive[base]      = f.x;
        g_drive[base + SS] = f.y;
    }
}

// ---------------- powers: (A^T)^32 via 5 fused squarings, single wave ----------------
__global__ void __launch_bounds__(256) k_powers() {
    __shared__ float sRow[2][SS];
    const int tid = threadIdx.x;
    const int k0  = blockIdx.x * 2;     // 128 CTAs x 2 rows

    const float* src = g_At;
    float*       dst = g_PA;
#pragma unroll 1
    for (int step = 0; step < 5; ++step) {
        sRow[0][tid] = src[(size_t)k0 * SS + tid];
        sRow[1][tid] = src[(size_t)(k0 + 1) * SS + tid];
        __syncthreads();
        float a0 = 0.f, a1 = 0.f;
#pragma unroll 4
        for (int j = 0; j < SS; ++j) {
            float b = src[(size_t)j * SS + tid];
            a0 = fmaf(sRow[0][j], b, a0);
            a1 = fmaf(sRow[1][j], b, a1);
        }
        dst[(size_t)k0 * SS + tid]       = a0;
        dst[(size_t)(k0 + 1) * SS + tid] = a1;
        // grid-wide barrier (all 128 CTAs resident: single wave)
        __syncthreads();
        if (tid == 0) {
            __threadfence();
            atomicAdd(&g_sync, 1u);
            unsigned target = 128u * (unsigned)(step + 1);
            while (*((volatile unsigned*)&g_sync) < target) { __nanosleep(64); }
        }
        __syncthreads();
        src = dst;
        dst = (dst == g_PA) ? g_PB : g_PA;
    }
    // after 5 squarings result lives in g_PA
}

// ======== shared inner body for pass1/pass3: one recurrence step ========
// sx: [k][PAD] state in smem; acc out; weight ring prefetched from g_At.
__device__ __forceinline__ void step_gemm(const float (*sx)[PAD], const float* wp,
                                          unsigned long long acc[16]) {
    float wv[8];
#pragma unroll
    for (int i = 0; i < 8; ++i) wv[i] = wp[(size_t)i * SS];

#pragma unroll 1
    for (int kt = 0; kt < 32; ++kt) {
        float wn[8];
        if (kt < 31) {
#pragma unroll
            for (int i = 0; i < 8; ++i) wn[i] = wp[(size_t)((kt + 1) * 8 + i) * SS];
        }
#pragma unroll
        for (int i = 0; i < 8; ++i) {
            const int k = kt * 8 + i;
            unsigned long long w2 = pack2(wv[i], wv[i]);
            const ulonglong2* xv = (const ulonglong2*)(&sx[k][0]);
#pragma unroll
            for (int q = 0; q < 8; ++q) {
                ulonglong2 v = xv[q];
                fma2(acc[2 * q],     v.x, w2);
                fma2(acc[2 * q + 1], v.y, w2);
            }
        }
#pragma unroll
        for (int i = 0; i < 8; ++i) wv[i] = wn[i];
    }
}

// ---------------- pass1: per-chunk zero-init scan, keep only chunk-end ----------------
__global__ void __launch_bounds__(256) k_pass1() {
    const int c  = blockIdx.x / NBT;            // chunk 0..CCH-2
    const int b0 = (blockIdx.x % NBT) * BT;
    const int s  = threadIdx.x;
    __shared__ __align__(16) float sx[SS][PAD];

    // j = 0: x1 = drive[t0]  (zero initial state)
    {
        const int t0 = c * LCH;
        const float* dr = g_drive + ((size_t)t0 * BB + b0) * SS + s;
#pragma unroll
        for (int r = 0; r < BT; ++r) sx[s][r] = dr[(size_t)r * SS];
    }
    __syncthreads();

#pragma unroll 1
    for (int j = 1; j < LCH; ++j) {
        const int t = c * LCH + j;
        // prefetch drive early (overlaps whole k-loop)
        float dpre[BT];
        const float* dr = g_drive + ((size_t)t * BB + b0) * SS + s;
#pragma unroll
        for (int r = 0; r < BT; ++r) dpre[r] = dr[(size_t)r * SS];

        unsigned long long acc[16];
#pragma unroll
        for (int p = 0; p < 16; ++p) acc[p] = 0ull;

        step_gemm(sx, g_At + s, acc);

#pragma unroll
        for (int p = 0; p < 16; ++p) add2(acc[p], pack2(dpre[2 * p], dpre[2 * p + 1]));

        __syncthreads();
        ulonglong2* qd = (ulonglong2*)(&sx[s][0]);
#pragma unroll
        for (int q = 0; q < 8; ++q) qd[q] = make_ulonglong2(acc[2 * q], acc[2 * q + 1]);
        __syncthreads();
    }
#pragma unroll
    for (int r = 0; r < BT; ++r)
        g_localEnd[((size_t)c * BB + b0 + r) * SS + s] = sx[s][r];
}

// ---------------- pass2: boundary recurrence (independent per batch row) ----------------
__global__ void __launch_bounds__(256) k_pass2(const float* __restrict__ x0) {
    const int b0 = blockIdx.x * 2;   // 32 CTAs x 2 batch rows
    const int s  = threadIdx.x;
    __shared__ __align__(8) float sxp[SS][2];

    float v0 = x0[(size_t)b0 * SS + s];
    float v1 = x0[(size_t)(b0 + 1) * SS + s];
    sxp[s][0] = v0; sxp[s][1] = v1;
    g_xstart[((size_t)b0) * SS + s]       = v0;
    g_xstart[((size_t)(b0 + 1)) * SS + s] = v1;
    __syncthreads();

#pragma unroll 1
    for (int c = 1; c < CCH; ++c) {
        float e0 = g_localEnd[((size_t)(c - 1) * BB + b0) * SS + s];
        float e1 = g_localEnd[((size_t)(c - 1) * BB + b0 + 1) * SS + s];
        unsigned long long acc[4];
#pragma unroll
        for (int u = 0; u < 4; ++u) acc[u] = 0ull;
        const float* wp = g_PA + s;   // (A^T)^32
#pragma unroll 4
        for (int k = 0; k < SS; k += 4) {
#pragma unroll
            for (int u = 0; u < 4; ++u) {
                float w = wp[(size_t)(k + u) * SS];
                unsigned long long w2 = pack2(w, w);
                unsigned long long xp = *(const unsigned long long*)(&sxp[k + u][0]);
                fma2(acc[u], xp, w2);
            }
        }
        add2(acc[0], acc[1]); add2(acc[2], acc[3]); add2(acc[0], acc[2]);
        float2 f = unpack2(acc[0]);
        f.x += e0;
        f.y += e1;
        __syncthreads();
        sxp[s][0] = f.x; sxp[s][1] = f.y;
        __syncthreads();
        g_xstart[((size_t)c * BB + b0) * SS + s]     = f.x;
        g_xstart[((size_t)c * BB + b0 + 1) * SS + s] = f.y;
    }
}

// ---------------- pass3: real scan per chunk from exact starts, emit X ----------------
__global__ void __launch_bounds__(256) k_pass3(float* __restrict__ out, int dup) {
    const int c  = blockIdx.x / NBT;            // chunk 0..CCH-1
    const int b0 = (blockIdx.x % NBT) * BT;
    const int s  = threadIdx.x;
    __shared__ __align__(16) float sx[SS][PAD];

#pragma unroll
    for (int r = 0; r < BT; ++r)
        sx[s][r] = g_xstart[((size_t)c * BB + b0 + r) * SS + s];
    __syncthreads();

    float* out2 = out + (size_t)TBS;

#pragma unroll 1
    for (int j = 0; j < LCH; ++j) {
        const int t = c * LCH + j;
        float dpre[BT];
        const float* dr = g_drive + ((size_t)t * BB + b0) * SS + s;
#pragma unroll
        for (int r = 0; r < BT; ++r) dpre[r] = dr[(size_t)r * SS];

        unsigned long long acc[16];
#pragma unroll
        for (int p = 0; p < 16; ++p) acc[p] = 0ull;

        step_gemm(sx, g_At + s, acc);

#pragma unroll
        for (int p = 0; p < 16; ++p) add2(acc[p], pack2(dpre[2 * p], dpre[2 * p + 1]));

        __syncthreads();
        ulonglong2* qd = (ulonglong2*)(&sx[s][0]);
#pragma unroll
        for (int q = 0; q < 8; ++q) qd[q] = make_ulonglong2(acc[2 * q], acc[2 * q + 1]);
        __syncthreads();

        size_t obase = ((size_t)t * BB + b0) * SS + s;
#pragma unroll
        for (int p = 0; p < 16; ++p) {
            float2 f = unpack2(acc[p]);
            size_t o0 = obase + (size_t)(2 * p) * SS;
            size_t o1 = obase + (size_t)(2 * p + 1) * SS;
            out[o0] = f.x; out[o1] = f.y;
            if (dup) { out2[o0] = f.x; out2[o1] = f.y; }
        }
    }
}

// ---------------- launcher ----------------
extern "C" void kernel_launch(void* const* d_in, const int* in_sizes, int n_in,
                              void* d_out, int out_size) {
    const float* x  = (const float*)d_in[0];
    const float* U  = (const float*)d_in[1];
    const float* D  = (const float*)d_in[2];
    const float* Aw = (const float*)d_in[3];
    const float* Bw = (const float*)d_in[4];
    const float* Ew = (const float*)d_in[5];
    float* out = (float*)d_out;
    int dup = (out_size >= 2 * TBS) ? 1 : 0;

    k_prep<<<(SS * SS + WK * SS + 255) / 256, 256>>>(Aw, Bw, Ew);   // launch 0
    k_drive<<<(TT * BB) / 32, 256>>>(U, D);                          // launch 1
    k_powers<<<SS / 2, 256>>>();                                     // launch 2
    k_pass1<<<(CCH - 1) * NBT, 256>>>();                             // launch 3
    k_pass2<<<BB / 2, 256>>>(x);                                     // launch 4
    k_pass3<<<CCH * NBT, 256>>>(out, dup);                           // launch 5 (ncu -s 5 lands here)
}

// round 4
// speedup vs baseline: 1.3067x; 1.1516x over previous
#include <cuda_runtime.h>
#include <cstdint>
#include <cstddef>

#define TT   2048
#define BB   64
#define SS   256
#define INK  64
#define DK   32
#define WK   (INK + DK)      // 96
#define CCH  64              // chunks
#define LCH  32              // chunk length (TT/CCH)
#define BT   32              // batch tile for pass1/pass3
#define NBT  (BB / BT)       // 2
#define TBS  (TT * BB * SS)  // 33,554,432
#define PAD  36              // smem row stride (floats), 144B (16B aligned)

// ---------------- device scratch (static; no runtime allocation) ----------------
__device__ float g_At[SS * SS];            // At[k][s] = A[s][k]
__device__ float g_Wt[WK * SS];            // Wt[i][s] = packed [Bw^T ; Ew^T]
__device__ float g_PA[SS * SS];            // power ping
__device__ float g_PB[SS * SS];            // power pong
__device__ float g_drive[TBS];             // drive[t,b,s]
__device__ float g_localEnd[(CCH - 1) * BB * SS];
__device__ float g_xstart[CCH * BB * SS];
__device__ unsigned g_sync;

// ---------------- packed f32x2 helpers ----------------
__device__ __forceinline__ void fma2(unsigned long long& acc,
                                     unsigned long long a, unsigned long long b) {
    asm("fma.rn.f32x2 %0, %1, %2, %0;" : "+l"(acc) : "l"(a), "l"(b));
}
__device__ __forceinline__ void add2(unsigned long long& acc, unsigned long long a) {
    asm("add.rn.f32x2 %0, %1, %0;" : "+l"(acc) : "l"(a));
}
__device__ __forceinline__ unsigned long long pack2(float lo, float hi) {
    unsigned long long r;
    asm("mov.b64 %0, {%1, %2};" : "=l"(r) : "f"(lo), "f"(hi));
    return r;
}
__device__ __forceinline__ float2 unpack2(unsigned long long v) {
    float2 f;
    asm("mov.b64 {%0, %1}, %2;" : "=f"(f.x), "=f"(f.y) : "l"(v));
    return f;
}

// ---------------- prep: transpose A, pack weights, reset barrier ----------------
__global__ void __launch_bounds__(256) k_prep(const float* __restrict__ A,
                                              const float* __restrict__ Bw,
                                              const float* __restrict__ Ew) {
    int idx = blockIdx.x * blockDim.x + threadIdx.x;
    if (idx == 0) g_sync = 0u;
    if (idx < SS * SS) {
        int k = idx / SS, s = idx % SS;
        g_At[idx] = A[s * SS + k];
    } else {
        int j = idx - SS * SS;
        if (j < WK * SS) {
            int i = j / SS, s = j % SS;
            g_Wt[j] = (i < INK) ? Bw[s * INK + i] : Ew[s * DK + (i - INK)];
        }
    }
}

// ======== shared GEMM core: acc[s0,s1][b-pairs] += W^T * x ========
// sx: [k][PAD] state (broadcast over threads); wbase = weight matrix + 2*tid
// (weights for the two adjacent s columns load as one LDG.64).
template <int KTILES>
__device__ __forceinline__ void gemm_tiles(const float (*sx)[PAD], const float* wbase,
                                           unsigned long long acc0[16],
                                           unsigned long long acc1[16]) {
    float2 wv[8];
#pragma unroll
    for (int i = 0; i < 8; ++i) wv[i] = *(const float2*)(wbase + (size_t)i * SS);

#pragma unroll 1
    for (int kt = 0; kt < KTILES; ++kt) {
        float2 wn[8];
        if (kt < KTILES - 1) {
#pragma unroll
            for (int i = 0; i < 8; ++i)
                wn[i] = *(const float2*)(wbase + (size_t)((kt + 1) * 8 + i) * SS);
        }
#pragma unroll
        for (int i = 0; i < 8; ++i) {
            const int k = kt * 8 + i;
            unsigned long long w0 = pack2(wv[i].x, wv[i].x);
            unsigned long long w1 = pack2(wv[i].y, wv[i].y);
            const ulonglong2* xv = (const ulonglong2*)(&sx[k][0]);
#pragma unroll
            for (int q = 0; q < 8; ++q) {
                ulonglong2 v = xv[q];
                fma2(acc0[2 * q],     v.x, w0);
                fma2(acc0[2 * q + 1], v.y, w0);
                fma2(acc1[2 * q],     v.x, w1);
                fma2(acc1[2 * q + 1], v.y, w1);
            }
        }
#pragma unroll
        for (int i = 0; i < 8; ++i) wv[i] = wn[i];
    }
}

// ---------------- drive: g_drive[t,b,s] = U@Bw^T + D@Ew^T ----------------
__global__ void __launch_bounds__(128) k_drive(const float* __restrict__ U,
                                               const float* __restrict__ D) {
    __shared__ __align__(16) float sRow[WK][PAD];   // [i][r]
    const int R0  = blockIdx.x * 32;                // 32 flattened (t,b) rows per CTA
    const int tid = threadIdx.x;
    const int s0  = 2 * tid;

    for (int e = tid; e < 32 * WK; e += 128) {
        int r = e / WK, i = e % WK;
        size_t R = (size_t)(R0 + r);
        sRow[i][r] = (i < INK) ? U[R * INK + i] : D[R * DK + (i - INK)];
    }
    __syncthreads();

    unsigned long long acc0[16], acc1[16];
#pragma unroll
    for (int p = 0; p < 16; ++p) { acc0[p] = 0ull; acc1[p] = 0ull; }

    gemm_tiles<WK / 8>(sRow, g_Wt + s0, acc0, acc1);

#pragma unroll
    for (int q = 0; q < 16; ++q) {
        float2 f0 = unpack2(acc0[q]);   // rows 2q, 2q+1 for s0
        float2 f1 = unpack2(acc1[q]);   // rows 2q, 2q+1 for s1
        *(float2*)(&g_drive[(size_t)(R0 + 2 * q) * SS + s0])     = make_float2(f0.x, f1.x);
        *(float2*)(&g_drive[(size_t)(R0 + 2 * q + 1) * SS + s0]) = make_float2(f0.y, f1.y);
    }
}

// ---------------- powers: (A^T)^32 via 5 fused squarings, single wave ----------------
__global__ void __launch_bounds__(256) k_powers() {
    __shared__ float sRow[2][SS];
    const int tid = threadIdx.x;
    const int k0  = blockIdx.x * 2;     // 128 CTAs x 2 rows

    const float* src = g_At;
    float*       dst = g_PA;
#pragma unroll 1
    for (int step = 0; step < 5; ++step) {
        sRow[0][tid] = src[(size_t)k0 * SS + tid];
        sRow[1][tid] = src[(size_t)(k0 + 1) * SS + tid];
        __syncthreads();
        float a0 = 0.f, a1 = 0.f;
#pragma unroll 4
        for (int j = 0; j < SS; ++j) {
            float b = src[(size_t)j * SS + tid];
            a0 = fmaf(sRow[0][j], b, a0);
            a1 = fmaf(sRow[1][j], b, a1);
        }
        dst[(size_t)k0 * SS + tid]       = a0;
        dst[(size_t)(k0 + 1) * SS + tid] = a1;
        __syncthreads();
        if (tid == 0) {
            __threadfence();
            atomicAdd(&g_sync, 1u);
            unsigned target = 128u * (unsigned)(step + 1);
            while (*((volatile unsigned*)&g_sync) < target) { __nanosleep(64); }
        }
        __syncthreads();
        src = dst;
        dst = (dst == g_PA) ? g_PB : g_PA;
    }
    // result = (A^T)^32 in g_PA
}

// ---------------- pass1: per-chunk zero-init scan, keep only chunk-end ----------------
__global__ void __launch_bounds__(128) k_pass1() {
    const int c   = blockIdx.x / NBT;           // chunk 0..CCH-2
    const int b0  = (blockIdx.x % NBT) * BT;
    const int tid = threadIdx.x;
    const int s0  = 2 * tid;
    __shared__ __align__(16) float sx[SS][PAD];

    // j = 0: x1 = drive[t0]  (zero initial state)
    {
        const int t0 = c * LCH;
#pragma unroll
        for (int r = 0; r < BT; ++r) {
            float2 d = *(const float2*)(&g_drive[((size_t)t0 * BB + b0 + r) * SS + s0]);
            sx[s0][r]     = d.x;
            sx[s0 + 1][r] = d.y;
        }
    }
    __syncthreads();

#pragma unroll 1
    for (int j = 1; j < LCH; ++j) {
        const int t = c * LCH + j;
        unsigned long long acc0[16], acc1[16];
#pragma unroll
        for (int p = 0; p < 16; ++p) { acc0[p] = 0ull; acc1[p] = 0ull; }

        gemm_tiles<SS / 8>(sx, g_At + s0, acc0, acc1);

        const float* dr = g_drive + ((size_t)t * BB + b0) * SS + s0;
#pragma unroll
        for (int q = 0; q < 16; ++q) {
            float2 da = *(const float2*)(dr + (size_t)(2 * q) * SS);
            float2 db = *(const float2*)(dr + (size_t)(2 * q + 1) * SS);
            add2(acc0[q], pack2(da.x, db.x));
            add2(acc1[q], pack2(da.y, db.y));
        }

        __syncthreads();
        ulonglong2* q0 = (ulonglong2*)(&sx[s0][0]);
        ulonglong2* q1 = (ulonglong2*)(&sx[s0 + 1][0]);
#pragma unroll
        for (int q = 0; q < 8; ++q) {
            q0[q] = make_ulonglong2(acc0[2 * q], acc0[2 * q + 1]);
            q1[q] = make_ulonglong2(acc1[2 * q], acc1[2 * q + 1]);
        }
        __syncthreads();
    }
#pragma unroll
    for (int r = 0; r < BT; ++r)
        *(float2*)(&g_localEnd[((size_t)c * BB + b0 + r) * SS + s0]) =
            make_float2(sx[s0][r], sx[s0 + 1][r]);
}

// ---------------- pass2: boundary recurrence (independent per batch row) ----------------
__global__ void __launch_bounds__(256) k_pass2(const float* __restrict__ x0) {
    const int b0 = blockIdx.x * 2;   // 32 CTAs x 2 batch rows
    const int s  = threadIdx.x;
    __shared__ __align__(8) float sxp[SS][2];

    float v0 = x0[(size_t)b0 * SS + s];
    float v1 = x0[(size_t)(b0 + 1) * SS + s];
    sxp[s][0] = v0; sxp[s][1] = v1;
    g_xstart[((size_t)b0) * SS + s]       = v0;
    g_xstart[((size_t)(b0 + 1)) * SS + s] = v1;
    __syncthreads();

#pragma unroll 1
    for (int c = 1; c < CCH; ++c) {
        float e0 = g_localEnd[((size_t)(c - 1) * BB + b0) * SS + s];
        float e1 = g_localEnd[((size_t)(c - 1) * BB + b0 + 1) * SS + s];
        unsigned long long acc[4];
#pragma unroll
        for (int u = 0; u < 4; ++u) acc[u] = 0ull;
        const float* wp = g_PA + s;   // (A^T)^32
#pragma unroll 4
        for (int k = 0; k < SS; k += 4) {
#pragma unroll
            for (int u = 0; u < 4; ++u) {
                float w = wp[(size_t)(k + u) * SS];
                unsigned long long w2 = pack2(w, w);
                unsigned long long xp = *(const unsigned long long*)(&sxp[k + u][0]);
                fma2(acc[u], xp, w2);
            }
        }
        add2(acc[0], acc[1]); add2(acc[2], acc[3]); add2(acc[0], acc[2]);
        float2 f = unpack2(acc[0]);
        f.x += e0;
        f.y += e1;
        __syncthreads();
        sxp[s][0] = f.x; sxp[s][1] = f.y;
        __syncthreads();
        g_xstart[((size_t)c * BB + b0) * SS + s]     = f.x;
        g_xstart[((size_t)c * BB + b0 + 1) * SS + s] = f.y;
    }
}

// ---------------- pass3: real scan per chunk from exact starts, emit X ----------------
__global__ void __launch_bounds__(128) k_pass3(float* __restrict__ out, int dup) {
    const int c   = blockIdx.x / NBT;           // chunk 0..CCH-1
    const int b0  = (blockIdx.x % NBT) * BT;
    const int tid = threadIdx.x;
    const int s0  = 2 * tid;
    __shared__ __align__(16) float sx[SS][PAD];

#pragma unroll
    for (int r = 0; r < BT; ++r) {
        float2 v = *(const float2*)(&g_xstart[((size_t)c * BB + b0 + r) * SS + s0]);
        sx[s0][r]     = v.x;
        sx[s0 + 1][r] = v.y;
    }
    __syncthreads();

    float* out2 = out + (size_t)TBS;

#pragma unroll 1
    for (int j = 0; j < LCH; ++j) {
        const int t = c * LCH + j;
        unsigned long long acc0[16], acc1[16];
#pragma unroll
        for (int p = 0; p < 16; ++p) { acc0[p] = 0ull; acc1[p] = 0ull; }

        gemm_tiles<SS / 8>(sx, g_At + s0, acc0, acc1);

        const float* dr = g_drive + ((size_t)t * BB + b0) * SS + s0;
#pragma unroll
        for (int q = 0; q < 16; ++q) {
            float2 da = *(const float2*)(dr + (size_t)(2 * q) * SS);
            float2 db = *(const float2*)(dr + (size_t)(2 * q + 1) * SS);
            add2(acc0[q], pack2(da.x, db.x));
            add2(acc1[q], pack2(da.y, db.y));
        }

        __syncthreads();
        ulonglong2* q0 = (ulonglong2*)(&sx[s0][0]);
        ulonglong2* q1 = (ulonglong2*)(&sx[s0 + 1][0]);
#pragma unroll
        for (int q = 0; q < 8; ++q) {
            q0[q] = make_ulonglong2(acc0[2 * q], acc0[2 * q + 1]);
            q1[q] = make_ulonglong2(acc1[2 * q], acc1[2 * q + 1]);
        }
        __syncthreads();

        size_t obase = ((size_t)t * BB + b0) * SS + s0;
#pragma unroll
        for (int q = 0; q < 16; ++q) {
            float2 f0 = unpack2(acc0[q]);
            float2 f1 = unpack2(acc1[q]);
            float2 oA = make_float2(f0.x, f1.x);
            float2 oB = make_float2(f0.y, f1.y);
            size_t oa = obase + (size_t)(2 * q) * SS;
            size_t ob = obase + (size_t)(2 * q + 1) * SS;
            *(float2*)(&out[oa]) = oA;
            *(float2*)(&out[ob]) = oB;
            if (dup) {
                *(float2*)(&out2[oa]) = oA;
                *(float2*)(&out2[ob]) = oB;
            }
        }
    }
}

// ---------------- launcher ----------------
extern "C" void kernel_launch(void* const* d_in, const int* in_sizes, int n_in,
                              void* d_out, int out_size) {
    const float* x  = (const float*)d_in[0];
    const float* U  = (const float*)d_in[1];
    const float* D  = (const float*)d_in[2];
    const float* Aw = (const float*)d_in[3];
    const float* Bw = (const float*)d_in[4];
    const float* Ew = (const float*)d_in[5];
    float* out = (float*)d_out;
    int dup = (out_size >= 2 * TBS) ? 1 : 0;

    k_prep<<<(SS * SS + WK * SS + 255) / 256, 256>>>(Aw, Bw, Ew);   // 0
    k_drive<<<(TT * BB) / 32, 128>>>(U, D);                          // 1
    k_powers<<<SS / 2, 256>>>();                                     // 2
    k_pass1<<<(CCH - 1) * NBT, 128>>>();                             // 3
    k_pass2<<<BB / 2, 256>>>(x);                                     // 4
    k_pass3<<<CCH * NBT, 128>>>(out, dup);                           // 5
}